// round 14
// baseline (speedup 1.0000x reference)
#include <cuda_runtime.h>

#define HH 128
#define WW 128
#define HW 16384

typedef unsigned long long u64;

__device__ __forceinline__ u64 pk2(float lo, float hi) {
    u64 r; asm("mov.b64 %0, {%1,%2};" : "=l"(r) : "f"(lo), "f"(hi)); return r;
}
__device__ __forceinline__ void upk2(u64 v, float& lo, float& hi) {
    asm("mov.b64 {%0,%1}, %2;" : "=f"(lo), "=f"(hi) : "l"(v));
}
__device__ __forceinline__ void ffma2(u64& d, u64 a, u64 b) {
    asm("fma.rn.f32x2 %0, %1, %2, %3;" : "=l"(d) : "l"(a), "l"(b), "l"(d));
}

// ---------------- scratch ----------------
__device__ float g_t0   [10 * 64 * HW];
__device__ float g_r    [10 * 64 * HW];
__device__ float g_cat  [8 * 128 * HW];
__device__ float g_supp [8 * 64 * HW];
__device__ float g_feaA [8 * 64 * HW];
__device__ float g_feaB [8 * 64 * HW];
__device__ float g_off  [8 * 144 * HW];
__device__ float g_im   [8 * 3 * HW];
__device__ float g_dwT  [4 * 576 * 64];
__device__ float g_srcT [8 * 64 * HW];   // px-major feaA (transpose kernel)
__device__ float g_suppT[8 * 64 * HW];   // px-major supp (from gather)
__device__ float g_srcTB[8 * 64 * HW];   // px-major deform dual output

// ================= smem-staged conv (R10/R12 mainloop) + multi-ogroup ===============
// Input tile (34x18 halo, 64 ch) staged ONCE; og_count output-groups of 16 computed
// sequentially, re-staging only weights. Chain per output: kk outer, c inner.
#define SPX   612          // 18*34
#define SPAD  65
#define CONV_SM_BYTES ((SPX * SPAD + 9 * 64 * 16) * 4)

template <bool RELU, bool ADD>
__global__ __launch_bounds__(256)
void conv3x3_sm_kernel(const float* __restrict__ in, const float* __restrict__ wgt,
                       const float* __restrict__ bias, const float* __restrict__ addsrc,
                       float* __restrict__ out, int Cout, int og_count)
{
    const int CIN = 64;
    const int zgroups = (Cout >> 4) / og_count;
    const int img   = blockIdx.z / zgroups;
    const int chunk = blockIdx.z - img * zgroups;
    const int tx0   = blockIdx.x << 5;   // 32-wide
    const int ty0   = blockIdx.y << 4;   // 16-high

    extern __shared__ float sm[];
    float* ssm = sm;                     // [px][c] stride SPAD
    float* wsm = sm + SPX * SPAD;        // [kk][c][16]

    const int t = threadIdx.x;

    // ---- stage input tile (all 64 ch) once ----
    {
        const float* inimg = in + (size_t)img * CIN * HW;
#pragma unroll
        for (int i0 = 0; i0 < 3; i0++) {
            int px = t + i0 * 256;
            if (px < SPX) {
                int r   = px / 34;
                int col = px - r * 34;
                int gy  = ty0 + r - 1;
                int gx  = tx0 + col - 1;
                float* dst = ssm + px * SPAD;
                if ((unsigned)gy < HH && (unsigned)gx < WW) {
                    const float* src = inimg + gy * WW + gx;
#pragma unroll 8
                    for (int c = 0; c < CIN; c++) dst[c] = __ldg(src + (size_t)c * HW);
                } else {
#pragma unroll 8
                    for (int c = 0; c < CIN; c++) dst[c] = 0.f;
                }
            }
        }
    }

    const int col = t & 31;
    const int row = t >> 5;              // 0..7 ; rows row, row+8

    float* outimg = out + (size_t)img * Cout * HW;
    const float* addimg = ADD ? (addsrc + (size_t)img * Cout * HW) : nullptr;
    const int gx = tx0 + col;

#pragma unroll 1
    for (int p = 0; p < og_count; p++) {
        const int obase = (chunk * og_count + p) << 4;
        __syncthreads();   // protect prior-pass wsm reads / act staging visibility
        for (int i = t; i < 9 * CIN * 16; i += 256) {
            int o  = i & 15;
            int r  = i >> 4;
            int kk = r >> 6;
            int c  = r & 63;
            wsm[i] = wgt[((size_t)(obase + o) * CIN + c) * 9 + kk];
        }
        __syncthreads();

        u64 acc2[2][8];
#pragma unroll
        for (int pp = 0; pp < 2; pp++)
#pragma unroll
            for (int o2 = 0; o2 < 8; o2++) acc2[pp][o2] = 0ull;

#pragma unroll 1
        for (int kk = 0; kk < 9; kk++) {
            const int ky = kk / 3;
            const int kx = kk - ky * 3;
            const float* p0 = ssm + ((row + ky) * 34 + col + kx) * SPAD;
            const float* p1 = p0 + 8 * 34 * SPAD;
            const float* wrow = wsm + kk * CIN * 16;
#pragma unroll 8
            for (int c = 0; c < CIN; c++) {
                float v0 = p0[c];
                float v1 = p1[c];
                u64 vp0 = pk2(v0, v0);
                u64 vp1 = pk2(v1, v1);
                const ulonglong2* wq = reinterpret_cast<const ulonglong2*>(wrow + c * 16);
#pragma unroll
                for (int j = 0; j < 4; j++) {
                    ulonglong2 w2 = wq[j];
                    ffma2(acc2[0][2 * j],     vp0, w2.x);
                    ffma2(acc2[0][2 * j + 1], vp0, w2.y);
                    ffma2(acc2[1][2 * j],     vp1, w2.x);
                    ffma2(acc2[1][2 * j + 1], vp1, w2.y);
                }
            }
        }

#pragma unroll
        for (int o2 = 0; o2 < 8; o2++) {
#pragma unroll
            for (int pp = 0; pp < 2; pp++) {
                float alo, ahi;
                upk2(acc2[pp][o2], alo, ahi);
                int gy = ty0 + row + 8 * pp;
#pragma unroll
                for (int half = 0; half < 2; half++) {
                    int oc = obase + 2 * o2 + half;
                    float val = (half ? ahi : alo) + bias[oc];
                    size_t oi = (size_t)oc * HW + gy * WW + gx;
                    if (ADD)  val += addimg[oi];
                    if (RELU) val = fmaxf(val, 0.f);
                    outimg[oi] = val;
                }
            }
        }
    }
}

// ---------------- generic 3x3 conv, 8 outs/block (Cin=3/128, Cout=3) ----------------
template <bool RELU, bool ADD>
__global__ __launch_bounds__(256)
void conv3x3_kernel(const float* __restrict__ in, const float* __restrict__ wgt,
                    const float* __restrict__ bias, const float* __restrict__ addsrc,
                    float* __restrict__ out, int Cin, int Cout)
{
    const int ogroups = (Cout + 7) >> 3;
    const int img   = blockIdx.z / ogroups;
    const int og    = blockIdx.z - img * ogroups;
    const int obase = og << 3;
    const int tx0   = blockIdx.x << 5;
    const int ty0   = blockIdx.y << 5;

    extern __shared__ float wsm8[];   // [kk][c][8]

    const int t    = threadIdx.x;
    const int col  = t & 31;
    const int row0 = (t >> 5) << 2;

    for (int i = t; i < 9 * Cin * 8; i += 256) {
        int o  = i & 7;
        int r  = i >> 3;
        int kk = r / Cin;
        int c  = r - kk * Cin;
        wsm8[i] = (obase + o < Cout)
                 ? wgt[((size_t)(obase + o) * Cin + c) * 9 + kk] : 0.f;
    }
    __syncthreads();

    u64 acc2[4][4];
#pragma unroll
    for (int p = 0; p < 4; p++)
#pragma unroll
        for (int o2 = 0; o2 < 4; o2++) acc2[p][o2] = 0ull;

    const float* inimg = in + (size_t)img * Cin * HW;

#pragma unroll 1
    for (int kk = 0; kk < 9; kk++) {
        const int ky = kk / 3 - 1;
        const int kx = kk - (kk / 3) * 3 - 1;
        const int gx = tx0 + col + kx;
        const bool xin = ((unsigned)gx < WW);
        const float* bp[4];
        bool inb[4];
#pragma unroll
        for (int p = 0; p < 4; p++) {
            int gy = ty0 + row0 + p + ky;
            inb[p] = xin && ((unsigned)gy < HH);
            bp[p]  = inimg + gy * WW + gx;
        }
        const float* wrow = wsm8 + kk * Cin * 8;
#pragma unroll 4
        for (int c = 0; c < Cin; c++) {
            float v0 = inb[0] ? __ldg(bp[0] + (size_t)c * HW) : 0.f;
            float v1 = inb[1] ? __ldg(bp[1] + (size_t)c * HW) : 0.f;
            float v2 = inb[2] ? __ldg(bp[2] + (size_t)c * HW) : 0.f;
            float v3 = inb[3] ? __ldg(bp[3] + (size_t)c * HW) : 0.f;
            u64 vp0 = pk2(v0, v0);
            u64 vp1 = pk2(v1, v1);
            u64 vp2 = pk2(v2, v2);
            u64 vp3 = pk2(v3, v3);
            const float* wc = wrow + c * 8;
#pragma unroll
            for (int o2 = 0; o2 < 4; o2++) {
                u64 wp = *reinterpret_cast<const u64*>(wc + 2 * o2);
                ffma2(acc2[0][o2], vp0, wp);
                ffma2(acc2[1][o2], vp1, wp);
                ffma2(acc2[2][o2], vp2, wp);
                ffma2(acc2[3][o2], vp3, wp);
            }
        }
    }

    float* outimg = out + (size_t)img * Cout * HW;
    const float* addimg = ADD ? (addsrc + (size_t)img * Cout * HW) : nullptr;
#pragma unroll
    for (int o2 = 0; o2 < 4; o2++) {
#pragma unroll
        for (int p = 0; p < 4; p++) {
            float alo, ahi;
            upk2(acc2[p][o2], alo, ahi);
            int gy = ty0 + row0 + p;
            int gx = tx0 + col;
#pragma unroll
            for (int half = 0; half < 2; half++) {
                int oc = obase + 2 * o2 + half;
                if (oc < Cout) {
                    float val = (half ? ahi : alo) + bias[oc];
                    size_t oi = (size_t)oc * HW + gy * WW + gx;
                    if (ADD)  val += addimg[oi];
                    if (RELU) val = fmaxf(val, 0.f);
                    outimg[oi] = val;
                }
            }
        }
    }
}

// ---------------- transpose (64,HW) -> (HW,64) per image ----------------
__global__ __launch_bounds__(256)
void transpose_src_kernel(const float* __restrict__ in, float* __restrict__ out)
{
    __shared__ float tl[32][33];
    const int p0  = blockIdx.x << 5;
    const int c0  = blockIdx.y << 5;
    const int img = blockIdx.z;
    const float* ii = in  + (size_t)img * 64 * HW;
    float*       oo = out + (size_t)img * 64 * HW;
    const int tx = threadIdx.x & 31;
    const int ty = threadIdx.x >> 5;
#pragma unroll
    for (int j = 0; j < 4; j++) {
        int c = c0 + ty + j * 8;
        tl[ty + j * 8][tx] = ii[(size_t)c * HW + p0 + tx];
    }
    __syncthreads();
#pragma unroll
    for (int j = 0; j < 4; j++) {
        int p = p0 + ty + j * 8;
        oo[(size_t)p * 64 + c0 + tx] = tl[tx][ty + j * 8];
    }
}

// ---------------- grouped deformable conv (G=8, K2=9, Cpg=8) ----------------
// Optional dual output: outT (px-major) written from the epilogue for the next
// deform stage, eliminating a separate transpose pass.
__global__ __launch_bounds__(256)
void deform_conv_kernel(const float* __restrict__ srcT,  // (8,HW,64) pixel-major
                        const float* __restrict__ off,   // (8,144,HW)
                        const float* __restrict__ wT,    // [576][64]
                        float* __restrict__ out,         // (8,64,HW)
                        float* __restrict__ outT)        // (8,HW,64) or null
{
    const int h   = blockIdx.x;
    const int img = blockIdx.y;

    __shared__ float s_sm[72 * 128];
    __shared__ float w_sm[36 * 64];

    const int t     = threadIdx.x;
    const int lane  = t & 31;
    const int obase = (t >> 5) << 3;

    u64 acc2[4][4];
#pragma unroll
    for (int i = 0; i < 4; i++)
#pragma unroll
        for (int o2 = 0; o2 < 4; o2++) acc2[i][o2] = 0ull;

    const float* simg   = srcT + (size_t)img * 64 * HW;
    const float* offrow = off  + (size_t)img * 144 * HW + h * WW;

    for (int g = 0; g < 8; g++) {
        __syncthreads();
        for (int task = t; task < 1152; task += 256) {
            const int px = task & 127;
            const int k  = task >> 7;
            float dy = offrow[(size_t)((g * 9 + k) * 2)     * HW + px];
            float dx = offrow[(size_t)((g * 9 + k) * 2 + 1) * HW + px];
            float py = __fadd_rn(__fadd_rn(dy, (float)h),  (float)(k / 3 - 1));
            float qx = __fadd_rn(__fadd_rn(dx, (float)px), (float)(k % 3 - 1));
            float y0f = floorf(py), x0f = floorf(qx);
            float wy = __fsub_rn(py, y0f), wx = __fsub_rn(qx, x0f);
            bool my0 = (y0f >=  0.f) && (y0f <= (float)(HH - 1));
            bool my1 = (y0f >= -1.f) && (y0f <= (float)(HH - 2));
            bool mx0 = (x0f >=  0.f) && (x0f <= (float)(WW - 1));
            bool mx1 = (x0f >= -1.f) && (x0f <= (float)(WW - 2));
            int yi0 = (int)fminf(fmaxf(y0f,       0.f), (float)(HH - 1));
            int xi0 = (int)fminf(fmaxf(x0f,       0.f), (float)(WW - 1));
            int yi1 = (int)fminf(fmaxf(y0f + 1.f, 0.f), (float)(HH - 1));
            int xi1 = (int)fminf(fmaxf(x0f + 1.f, 0.f), (float)(WW - 1));
            float omy = __fsub_rn(1.f, wy), omx = __fsub_rn(1.f, wx);
            float w00 = __fmul_rn(__fmul_rn(omy, omx), (my0 && mx0) ? 1.f : 0.f);
            float w01 = __fmul_rn(__fmul_rn(omy, wx),  (my0 && mx1) ? 1.f : 0.f);
            float w10 = __fmul_rn(__fmul_rn(wy, omx),  (my1 && mx0) ? 1.f : 0.f);
            float w11 = __fmul_rn(__fmul_rn(wy, wx),   (my1 && mx1) ? 1.f : 0.f);
            int i00 = yi0 * WW + xi0, i01 = yi0 * WW + xi1;
            int i10 = yi1 * WW + xi0, i11 = yi1 * WW + xi1;
            const int g8 = g * 8;
            const float4* q00 = reinterpret_cast<const float4*>(simg + (size_t)i00 * 64 + g8);
            const float4* q01 = reinterpret_cast<const float4*>(simg + (size_t)i01 * 64 + g8);
            const float4* q10 = reinterpret_cast<const float4*>(simg + (size_t)i10 * 64 + g8);
            const float4* q11 = reinterpret_cast<const float4*>(simg + (size_t)i11 * 64 + g8);
            float4 a0 = q00[0], a1 = q00[1];
            float4 b0 = q01[0], b1 = q01[1];
            float4 c0 = q10[0], c1 = q10[1];
            float4 d0 = q11[0], d1 = q11[1];
            float va[8] = {a0.x, a0.y, a0.z, a0.w, a1.x, a1.y, a1.z, a1.w};
            float vb[8] = {b0.x, b0.y, b0.z, b0.w, b1.x, b1.y, b1.z, b1.w};
            float vc[8] = {c0.x, c0.y, c0.z, c0.w, c1.x, c1.y, c1.z, c1.w};
            float vd[8] = {d0.x, d0.y, d0.z, d0.w, d1.x, d1.y, d1.z, d1.w};
#pragma unroll
            for (int c = 0; c < 8; c++) {
                float v = __fadd_rn(
                            __fadd_rn(
                              __fadd_rn(__fmul_rn(va[c], w00),
                                        __fmul_rn(vb[c], w01)),
                              __fmul_rn(vc[c], w10)),
                            __fmul_rn(vd[c], w11));
                s_sm[(c * 9 + k) * 128 + px] = v;
            }
        }
#pragma unroll 1
        for (int half = 0; half < 2; half++) {
            __syncthreads();
            for (int i = t; i < 36 * 64; i += 256)
                w_sm[i] = wT[(size_t)(g * 72 + half * 36) * 64 + i];
            __syncthreads();
            const float* srow = s_sm + half * 36 * 128;
#pragma unroll 4
            for (int ck = 0; ck < 36; ck++) {
                u64 sp0 = pk2(srow[ck * 128 + lane],      srow[ck * 128 + lane]);
                u64 sp1 = pk2(srow[ck * 128 + lane + 32], srow[ck * 128 + lane + 32]);
                u64 sp2 = pk2(srow[ck * 128 + lane + 64], srow[ck * 128 + lane + 64]);
                u64 sp3 = pk2(srow[ck * 128 + lane + 96], srow[ck * 128 + lane + 96]);
                const ulonglong2* wq = reinterpret_cast<const ulonglong2*>(w_sm + ck * 64 + obase);
#pragma unroll
                for (int j = 0; j < 2; j++) {
                    ulonglong2 w2 = wq[j];
                    ffma2(acc2[0][2 * j],     sp0, w2.x);
                    ffma2(acc2[0][2 * j + 1], sp0, w2.y);
                    ffma2(acc2[1][2 * j],     sp1, w2.x);
                    ffma2(acc2[1][2 * j + 1], sp1, w2.y);
                    ffma2(acc2[2][2 * j],     sp2, w2.x);
                    ffma2(acc2[2][2 * j + 1], sp2, w2.y);
                    ffma2(acc2[3][2 * j],     sp3, w2.x);
                    ffma2(acc2[3][2 * j + 1], sp3, w2.y);
                }
            }
        }
    }

    float* outrow = out + (size_t)img * 64 * HW + h * WW;
    float* outTrow = outT ? (outT + ((size_t)img * HW + h * WW) * 64) : nullptr;
#pragma unroll
    for (int o2 = 0; o2 < 4; o2++)
#pragma unroll
        for (int i = 0; i < 4; i++) {
            float alo, ahi;
            upk2(acc2[i][o2], alo, ahi);
            outrow[(size_t)(obase + 2 * o2)     * HW + lane + 32 * i] = alo;
            outrow[(size_t)(obase + 2 * o2 + 1) * HW + lane + 32 * i] = ahi;
            if (outTrow) {
                float2 v2 = make_float2(alo, ahi);
                *reinterpret_cast<float2*>(outTrow + (size_t)(lane + 32 * i) * 64
                                           + obase + 2 * o2) = v2;
            }
        }
}

// ---------------- small utility kernels ----------------
__global__ void transpose_dw_kernel(const float* __restrict__ dw, float* __restrict__ dwT)
{
    int idx = blockIdx.x * blockDim.x + threadIdx.x;
    if (idx < 4 * 64 * 576) {
        int i  = idx / (64 * 576);
        int r  = idx - i * (64 * 576);
        int o  = r / 576;
        int ck = r - o * 576;
        dwT[(size_t)i * (576 * 64) + ck * 64 + o] = dw[idx];
    }
}

__global__ void gather_kernel(const float* __restrict__ t0, float* __restrict__ cat,
                              float* __restrict__ supp, float* __restrict__ suppT)
{
    const size_t total = (size_t)8 * 64 * HW;
    for (size_t idx = (size_t)blockIdx.x * blockDim.x + threadIdx.x; idx < total;
         idx += (size_t)gridDim.x * blockDim.x) {
        int j = (int)(idx / (64 * HW));
        size_t rem = idx - (size_t)j * (64 * HW);
        int c  = (int)(rem >> 14);          // rem / HW
        int hw = (int)(rem & (HW - 1));
        int b = j >> 2, slot = j & 3;
        int s = slot + (slot >= 2 ? 1 : 0);
        float ref = t0[(size_t)(b * 5 + 2) * 64 * HW + rem];
        float sp  = t0[(size_t)(b * 5 + s) * 64 * HW + rem];
        cat[(size_t)j * 128 * HW + rem]           = ref;
        cat[((size_t)j * 128 + 64) * HW + rem]    = sp;
        supp[idx] = sp;
        suppT[((size_t)j * HW + hw) * 64 + c] = sp;
    }
}

__global__ void scatter_kernel(const float* __restrict__ x,
                               const float* __restrict__ t0,
                               const float* __restrict__ im,
                               const float* __restrict__ fea,
                               float* __restrict__ out)
{
    const size_t LRS = (size_t)2 * 5 * 3 * HW;
    const size_t TOT = LRS + (size_t)2 * 5 * 64 * HW;
    for (size_t idx = (size_t)blockIdx.x * blockDim.x + threadIdx.x; idx < TOT;
         idx += (size_t)gridDim.x * blockDim.x) {
        if (idx < LRS) {
            int hw = (int)(idx % HW);
            int r  = (int)(idx / HW);
            int c = r % 3; r /= 3;
            int n = r % 5; int b = r / 5;
            float v;
            if (n == 2) {
                v = x[((size_t)(b * 5 + 2) * 3 + c) * HW + hw];
            } else {
                int j = b * 4 + (n < 2 ? n : n - 1);
                v = im[((size_t)j * 3 + c) * HW + hw];
            }
            out[idx] = v;
        } else {
            size_t kk = idx - LRS;
            int hw = (int)(kk % HW);
            int r  = (int)(kk / HW);
            int c = r % 64; r /= 64;
            int n = r % 5; int b = r / 5;
            float v;
            if (n == 2) {
                v = t0[((size_t)(b * 5 + 2) * 64 + c) * HW + hw];
            } else {
                int j = b * 4 + (n < 2 ? n : n - 1);
                v = fea[((size_t)j * 64 + c) * HW + hw];
            }
            out[idx] = v;
        }
    }
}

// ---------------- host ----------------
static void launch_conv8(const float* in, const float* w, const float* b,
                         const float* add, float* out, int Cin, int Cout, int nimg,
                         bool relu, bool addf)
{
    dim3 grid(4, 4, nimg * ((Cout + 7) / 8));
    size_t shmem = (size_t)9 * Cin * 8 * sizeof(float);
    if (relu)      conv3x3_kernel<true,  false><<<grid, 256, shmem>>>(in, w, b, nullptr, out, Cin, Cout);
    else if (addf) conv3x3_kernel<false, true ><<<grid, 256, shmem>>>(in, w, b, add,     out, Cin, Cout);
    else           conv3x3_kernel<false, false><<<grid, 256, shmem>>>(in, w, b, nullptr, out, Cin, Cout);
}

static void launch_conv_sm(const float* in, const float* w, const float* b,
                           const float* add, float* out, int Cout, int nimg,
                           int og_count, bool relu, bool addf)
{
    dim3 grid(4, 8, nimg * ((Cout >> 4) / og_count));
    if (relu) {
        cudaFuncSetAttribute(conv3x3_sm_kernel<true, false>,
                             cudaFuncAttributeMaxDynamicSharedMemorySize, CONV_SM_BYTES);
        conv3x3_sm_kernel<true, false><<<grid, 256, CONV_SM_BYTES>>>(in, w, b, nullptr, out, Cout, og_count);
    } else if (addf) {
        cudaFuncSetAttribute(conv3x3_sm_kernel<false, true>,
                             cudaFuncAttributeMaxDynamicSharedMemorySize, CONV_SM_BYTES);
        conv3x3_sm_kernel<false, true><<<grid, 256, CONV_SM_BYTES>>>(in, w, b, add, out, Cout, og_count);
    } else {
        cudaFuncSetAttribute(conv3x3_sm_kernel<false, false>,
                             cudaFuncAttributeMaxDynamicSharedMemorySize, CONV_SM_BYTES);
        conv3x3_sm_kernel<false, false><<<grid, 256, CONV_SM_BYTES>>>(in, w, b, nullptr, out, Cout, og_count);
    }
}

extern "C" void kernel_launch(void* const* d_in, const int* in_sizes, int n_in,
                              void* d_out, int out_size)
{
    const float* x    = (const float*)d_in[0];
    const float* cfw  = (const float*)d_in[1];
    const float* cfb  = (const float*)d_in[2];
    const float* rw1  = (const float*)d_in[3];
    const float* rb1  = (const float*)d_in[4];
    const float* rw2  = (const float*)d_in[5];
    const float* rb2  = (const float*)d_in[6];
    const float* crw  = (const float*)d_in[7];
    const float* crb  = (const float*)d_in[8];
    const float* offw = (const float*)d_in[9];
    const float* offb = (const float*)d_in[10];
    const float* dw   = (const float*)d_in[11];
    const float* rcw  = (const float*)d_in[12];
    const float* rcb  = (const float*)d_in[13];
    float* out = (float*)d_out;

    float *t0, *rbuf, *cat, *supp, *feaA, *feaB, *offbuf, *im, *dwT, *srcT, *suppT, *srcTB;
    cudaGetSymbolAddress((void**)&t0,    g_t0);
    cudaGetSymbolAddress((void**)&rbuf,  g_r);
    cudaGetSymbolAddress((void**)&cat,   g_cat);
    cudaGetSymbolAddress((void**)&supp,  g_supp);
    cudaGetSymbolAddress((void**)&feaA,  g_feaA);
    cudaGetSymbolAddress((void**)&feaB,  g_feaB);
    cudaGetSymbolAddress((void**)&offbuf,g_off);
    cudaGetSymbolAddress((void**)&im,    g_im);
    cudaGetSymbolAddress((void**)&dwT,   g_dwT);
    cudaGetSymbolAddress((void**)&srcT,  g_srcT);
    cudaGetSymbolAddress((void**)&suppT, g_suppT);
    cudaGetSymbolAddress((void**)&srcTB, g_srcTB);

    transpose_dw_kernel<<<(4 * 64 * 576 + 255) / 256, 256>>>(dw, dwT);

    // conv_first + ReLU : (10,3) -> (10,64)
    launch_conv8(x, cfw, cfb, nullptr, t0, 3, 64, 10, true, false);

    // 5 residual blocks (2 ogroups per block)
    for (int i = 0; i < 5; i++) {
        launch_conv_sm(t0,   rw1 + (size_t)i * 36864, rb1 + i * 64, nullptr, rbuf, 64, 10, 2, true,  false);
        launch_conv_sm(rbuf, rw2 + (size_t)i * 36864, rb2 + i * 64, t0,      t0,   64, 10, 2, false, true);
    }

    // build concat(ref, supp), supp and px-major suppT
    gather_kernel<<<4096, 256>>>(t0, cat, supp, suppT);

    // cr conv: 128 -> 64
    launch_conv8(cat, crw, crb, nullptr, feaA, 128, 64, 8, false, false);

    const dim3 tgrid(512, 2, 8);
    const dim3 dgrid(128, 8);

    // PCD cascade (offset convs: 3 ogroups per block)
    launch_conv_sm(feaA, offw,              offb,       nullptr, offbuf, 144, 8, 3, false, false);
    transpose_src_kernel<<<tgrid, 256>>>(feaA, srcT);
    deform_conv_kernel<<<dgrid, 256>>>(srcT, offbuf, dwT,             feaB, srcTB);

    launch_conv_sm(feaB, offw + 82944,      offb + 144, nullptr, offbuf, 144, 8, 3, false, false);
    deform_conv_kernel<<<dgrid, 256>>>(srcTB, offbuf, dwT + 36864,    feaA, nullptr);

    launch_conv_sm(feaA, offw + 2 * 82944,  offb + 288, nullptr, offbuf, 144, 8, 3, false, false);
    deform_conv_kernel<<<dgrid, 256>>>(suppT, offbuf, dwT + 2 * 36864, feaB, srcTB);  // fea

    launch_conv_sm(feaB, offw + 3 * 82944,  offb + 432, nullptr, offbuf, 144, 8, 3, false, false);
    deform_conv_kernel<<<dgrid, 256>>>(srcTB, offbuf, dwT + 3 * 36864, feaA, nullptr); // aligned

    // recon conv: 64 -> 3
    launch_conv8(feaA, rcw, rcb, nullptr, im, 64, 3, 8, false, false);

    // assemble outputs (lrs | feats)
    scatter_kernel<<<4096, 256>>>(x, t0, im, feaB, out);
}

// round 15
// speedup vs baseline: 1.0880x; 1.0880x over previous
#include <cuda_runtime.h>

#define HH 128
#define WW 128
#define HW 16384

typedef unsigned long long u64;

__device__ __forceinline__ u64 pk2(float lo, float hi) {
    u64 r; asm("mov.b64 %0, {%1,%2};" : "=l"(r) : "f"(lo), "f"(hi)); return r;
}
__device__ __forceinline__ void upk2(u64 v, float& lo, float& hi) {
    asm("mov.b64 {%0,%1}, %2;" : "=f"(lo), "=f"(hi) : "l"(v));
}
__device__ __forceinline__ void ffma2(u64& d, u64 a, u64 b) {
    asm("fma.rn.f32x2 %0, %1, %2, %3;" : "=l"(d) : "l"(a), "l"(b), "l"(d));
}

// ---------------- scratch ----------------
__device__ float g_t0   [10 * 64 * HW];
__device__ float g_r    [10 * 64 * HW];
__device__ float g_cat  [8 * 128 * HW];
__device__ float g_supp [8 * 64 * HW];
__device__ float g_feaA [8 * 64 * HW];
__device__ float g_feaB [8 * 64 * HW];
__device__ float g_off  [8 * 144 * HW];
__device__ float g_im   [8 * 3 * HW];
__device__ float g_dwT  [4 * 576 * 64];
__device__ float g_srcT [8 * 64 * HW];   // px-major feaA (transpose kernel)
__device__ float g_suppT[8 * 64 * HW];   // px-major supp (from gather)
__device__ float g_srcTB[8 * 64 * HW];   // px-major deform dual output

// ================= smem-staged conv (R12 winner): Cin=64, 16 outs, 32x16, 256 thr ====
#define SPX   612          // 18*34
#define SPAD  65
#define CONV_SM_BYTES ((SPX * SPAD + 9 * 64 * 16) * 4)

template <bool RELU, bool ADD>
__global__ __launch_bounds__(256)
void conv3x3_sm_kernel(const float* __restrict__ in, const float* __restrict__ wgt,
                       const float* __restrict__ bias, const float* __restrict__ addsrc,
                       float* __restrict__ out, int Cout)
{
    const int CIN = 64;
    const int ogroups = Cout >> 4;
    const int img   = blockIdx.z / ogroups;
    const int og    = blockIdx.z - img * ogroups;
    const int obase = og << 4;
    const int tx0   = blockIdx.x << 5;   // 32-wide
    const int ty0   = blockIdx.y << 4;   // 16-high

    extern __shared__ float sm[];
    float* ssm = sm;                     // [px][c] stride SPAD
    float* wsm = sm + SPX * SPAD;        // [kk][c][16]

    const int t = threadIdx.x;

    {
        const float* inimg = in + (size_t)img * CIN * HW;
#pragma unroll
        for (int i0 = 0; i0 < 3; i0++) {
            int px = t + i0 * 256;
            if (px < SPX) {
                int r   = px / 34;
                int col = px - r * 34;
                int gy  = ty0 + r - 1;
                int gx  = tx0 + col - 1;
                float* dst = ssm + px * SPAD;
                if ((unsigned)gy < HH && (unsigned)gx < WW) {
                    const float* src = inimg + gy * WW + gx;
#pragma unroll 8
                    for (int c = 0; c < CIN; c++) dst[c] = __ldg(src + (size_t)c * HW);
                } else {
#pragma unroll 8
                    for (int c = 0; c < CIN; c++) dst[c] = 0.f;
                }
            }
        }
        for (int i = t; i < 9 * CIN * 16; i += 256) {
            int o  = i & 15;
            int r  = i >> 4;
            int kk = r >> 6;
            int c  = r & 63;
            wsm[i] = wgt[((size_t)(obase + o) * CIN + c) * 9 + kk];
        }
    }
    __syncthreads();

    const int col = t & 31;
    const int row = t >> 5;              // 0..7 ; rows row, row+8

    u64 acc2[2][8];
#pragma unroll
    for (int p = 0; p < 2; p++)
#pragma unroll
        for (int o2 = 0; o2 < 8; o2++) acc2[p][o2] = 0ull;

#pragma unroll 1
    for (int kk = 0; kk < 9; kk++) {
        const int ky = kk / 3;
        const int kx = kk - ky * 3;
        const float* p0 = ssm + ((row + ky) * 34 + col + kx) * SPAD;
        const float* p1 = p0 + 8 * 34 * SPAD;
        const float* wrow = wsm + kk * CIN * 16;
#pragma unroll 8
        for (int c = 0; c < CIN; c++) {
            float v0 = p0[c];
            float v1 = p1[c];
            u64 vp0 = pk2(v0, v0);
            u64 vp1 = pk2(v1, v1);
            const ulonglong2* wq = reinterpret_cast<const ulonglong2*>(wrow + c * 16);
#pragma unroll
            for (int j = 0; j < 4; j++) {
                ulonglong2 w2 = wq[j];
                ffma2(acc2[0][2 * j],     vp0, w2.x);
                ffma2(acc2[0][2 * j + 1], vp0, w2.y);
                ffma2(acc2[1][2 * j],     vp1, w2.x);
                ffma2(acc2[1][2 * j + 1], vp1, w2.y);
            }
        }
    }

    float* outimg = out + (size_t)img * Cout * HW;
    const float* addimg = ADD ? (addsrc + (size_t)img * Cout * HW) : nullptr;
    const int gx = tx0 + col;
#pragma unroll
    for (int o2 = 0; o2 < 8; o2++) {
#pragma unroll
        for (int p = 0; p < 2; p++) {
            float alo, ahi;
            upk2(acc2[p][o2], alo, ahi);
            int gy = ty0 + row + 8 * p;
#pragma unroll
            for (int half = 0; half < 2; half++) {
                int oc = obase + 2 * o2 + half;
                float val = (half ? ahi : alo) + bias[oc];
                size_t oi = (size_t)oc * HW + gy * WW + gx;
                if (ADD)  val += addimg[oi];
                if (RELU) val = fmaxf(val, 0.f);
                outimg[oi] = val;
            }
        }
    }
}

// ---------------- generic 3x3 conv, 8 outs/block (Cin=3/128, Cout=3) ----------------
template <bool RELU, bool ADD>
__global__ __launch_bounds__(256)
void conv3x3_kernel(const float* __restrict__ in, const float* __restrict__ wgt,
                    const float* __restrict__ bias, const float* __restrict__ addsrc,
                    float* __restrict__ out, int Cin, int Cout)
{
    const int ogroups = (Cout + 7) >> 3;
    const int img   = blockIdx.z / ogroups;
    const int og    = blockIdx.z - img * ogroups;
    const int obase = og << 3;
    const int tx0   = blockIdx.x << 5;
    const int ty0   = blockIdx.y << 5;

    extern __shared__ float wsm8[];   // [kk][c][8]

    const int t    = threadIdx.x;
    const int col  = t & 31;
    const int row0 = (t >> 5) << 2;

    for (int i = t; i < 9 * Cin * 8; i += 256) {
        int o  = i & 7;
        int r  = i >> 3;
        int kk = r / Cin;
        int c  = r - kk * Cin;
        wsm8[i] = (obase + o < Cout)
                 ? wgt[((size_t)(obase + o) * Cin + c) * 9 + kk] : 0.f;
    }
    __syncthreads();

    u64 acc2[4][4];
#pragma unroll
    for (int p = 0; p < 4; p++)
#pragma unroll
        for (int o2 = 0; o2 < 4; o2++) acc2[p][o2] = 0ull;

    const float* inimg = in + (size_t)img * Cin * HW;

#pragma unroll 1
    for (int kk = 0; kk < 9; kk++) {
        const int ky = kk / 3 - 1;
        const int kx = kk - (kk / 3) * 3 - 1;
        const int gx = tx0 + col + kx;
        const bool xin = ((unsigned)gx < WW);
        const float* bp[4];
        bool inb[4];
#pragma unroll
        for (int p = 0; p < 4; p++) {
            int gy = ty0 + row0 + p + ky;
            inb[p] = xin && ((unsigned)gy < HH);
            bp[p]  = inimg + gy * WW + gx;
        }
        const float* wrow = wsm8 + kk * Cin * 8;
#pragma unroll 4
        for (int c = 0; c < Cin; c++) {
            float v0 = inb[0] ? __ldg(bp[0] + (size_t)c * HW) : 0.f;
            float v1 = inb[1] ? __ldg(bp[1] + (size_t)c * HW) : 0.f;
            float v2 = inb[2] ? __ldg(bp[2] + (size_t)c * HW) : 0.f;
            float v3 = inb[3] ? __ldg(bp[3] + (size_t)c * HW) : 0.f;
            u64 vp0 = pk2(v0, v0);
            u64 vp1 = pk2(v1, v1);
            u64 vp2 = pk2(v2, v2);
            u64 vp3 = pk2(v3, v3);
            const float* wc = wrow + c * 8;
#pragma unroll
            for (int o2 = 0; o2 < 4; o2++) {
                u64 wp = *reinterpret_cast<const u64*>(wc + 2 * o2);
                ffma2(acc2[0][o2], vp0, wp);
                ffma2(acc2[1][o2], vp1, wp);
                ffma2(acc2[2][o2], vp2, wp);
                ffma2(acc2[3][o2], vp3, wp);
            }
        }
    }

    float* outimg = out + (size_t)img * Cout * HW;
    const float* addimg = ADD ? (addsrc + (size_t)img * Cout * HW) : nullptr;
#pragma unroll
    for (int o2 = 0; o2 < 4; o2++) {
#pragma unroll
        for (int p = 0; p < 4; p++) {
            float alo, ahi;
            upk2(acc2[p][o2], alo, ahi);
            int gy = ty0 + row0 + p;
            int gx = tx0 + col;
#pragma unroll
            for (int half = 0; half < 2; half++) {
                int oc = obase + 2 * o2 + half;
                if (oc < Cout) {
                    float val = (half ? ahi : alo) + bias[oc];
                    size_t oi = (size_t)oc * HW + gy * WW + gx;
                    if (ADD)  val += addimg[oi];
                    if (RELU) val = fmaxf(val, 0.f);
                    outimg[oi] = val;
                }
            }
        }
    }
}

// ---------------- transpose (64,HW) -> (HW,64) per image ----------------
__global__ __launch_bounds__(256)
void transpose_src_kernel(const float* __restrict__ in, float* __restrict__ out)
{
    __shared__ float tl[32][33];
    const int p0  = blockIdx.x << 5;
    const int c0  = blockIdx.y << 5;
    const int img = blockIdx.z;
    const float* ii = in  + (size_t)img * 64 * HW;
    float*       oo = out + (size_t)img * 64 * HW;
    const int tx = threadIdx.x & 31;
    const int ty = threadIdx.x >> 5;
#pragma unroll
    for (int j = 0; j < 4; j++) {
        int c = c0 + ty + j * 8;
        tl[ty + j * 8][tx] = ii[(size_t)c * HW + p0 + tx];
    }
    __syncthreads();
#pragma unroll
    for (int j = 0; j < 4; j++) {
        int p = p0 + ty + j * 8;
        oo[(size_t)p * 64 + c0 + tx] = tl[tx][ty + j * 8];
    }
}

// ---------------- grouped deformable conv (G=8, K2=9, Cpg=8) ----------------
// Optional dual output: outT (px-major) written in the epilogue for the next stage.
__global__ __launch_bounds__(256)
void deform_conv_kernel(const float* __restrict__ srcT,  // (8,HW,64) pixel-major
                        const float* __restrict__ off,   // (8,144,HW)
                        const float* __restrict__ wT,    // [576][64]
                        float* __restrict__ out,         // (8,64,HW)
                        float* __restrict__ outT)        // (8,HW,64) or null
{
    const int h   = blockIdx.x;
    const int img = blockIdx.y;

    __shared__ float s_sm[72 * 128];
    __shared__ float w_sm[36 * 64];

    const int t     = threadIdx.x;
    const int lane  = t & 31;
    const int obase = (t >> 5) << 3;

    u64 acc2[4][4];
#pragma unroll
    for (int i = 0; i < 4; i++)
#pragma unroll
        for (int o2 = 0; o2 < 4; o2++) acc2[i][o2] = 0ull;

    const float* simg   = srcT + (size_t)img * 64 * HW;
    const float* offrow = off  + (size_t)img * 144 * HW + h * WW;

    for (int g = 0; g < 8; g++) {
        __syncthreads();
        for (int task = t; task < 1152; task += 256) {
            const int px = task & 127;
            const int k  = task >> 7;
            float dy = offrow[(size_t)((g * 9 + k) * 2)     * HW + px];
            float dx = offrow[(size_t)((g * 9 + k) * 2 + 1) * HW + px];
            float py = __fadd_rn(__fadd_rn(dy, (float)h),  (float)(k / 3 - 1));
            float qx = __fadd_rn(__fadd_rn(dx, (float)px), (float)(k % 3 - 1));
            float y0f = floorf(py), x0f = floorf(qx);
            float wy = __fsub_rn(py, y0f), wx = __fsub_rn(qx, x0f);
            bool my0 = (y0f >=  0.f) && (y0f <= (float)(HH - 1));
            bool my1 = (y0f >= -1.f) && (y0f <= (float)(HH - 2));
            bool mx0 = (x0f >=  0.f) && (x0f <= (float)(WW - 1));
            bool mx1 = (x0f >= -1.f) && (x0f <= (float)(WW - 2));
            int yi0 = (int)fminf(fmaxf(y0f,       0.f), (float)(HH - 1));
            int xi0 = (int)fminf(fmaxf(x0f,       0.f), (float)(WW - 1));
            int yi1 = (int)fminf(fmaxf(y0f + 1.f, 0.f), (float)(HH - 1));
            int xi1 = (int)fminf(fmaxf(x0f + 1.f, 0.f), (float)(WW - 1));
            float omy = __fsub_rn(1.f, wy), omx = __fsub_rn(1.f, wx);
            float w00 = __fmul_rn(__fmul_rn(omy, omx), (my0 && mx0) ? 1.f : 0.f);
            float w01 = __fmul_rn(__fmul_rn(omy, wx),  (my0 && mx1) ? 1.f : 0.f);
            float w10 = __fmul_rn(__fmul_rn(wy, omx),  (my1 && mx0) ? 1.f : 0.f);
            float w11 = __fmul_rn(__fmul_rn(wy, wx),   (my1 && mx1) ? 1.f : 0.f);
            int i00 = yi0 * WW + xi0, i01 = yi0 * WW + xi1;
            int i10 = yi1 * WW + xi0, i11 = yi1 * WW + xi1;
            const int g8 = g * 8;
            const float4* q00 = reinterpret_cast<const float4*>(simg + (size_t)i00 * 64 + g8);
            const float4* q01 = reinterpret_cast<const float4*>(simg + (size_t)i01 * 64 + g8);
            const float4* q10 = reinterpret_cast<const float4*>(simg + (size_t)i10 * 64 + g8);
            const float4* q11 = reinterpret_cast<const float4*>(simg + (size_t)i11 * 64 + g8);
            float4 a0 = q00[0], a1 = q00[1];
            float4 b0 = q01[0], b1 = q01[1];
            float4 c0 = q10[0], c1 = q10[1];
            float4 d0 = q11[0], d1 = q11[1];
            float va[8] = {a0.x, a0.y, a0.z, a0.w, a1.x, a1.y, a1.z, a1.w};
            float vb[8] = {b0.x, b0.y, b0.z, b0.w, b1.x, b1.y, b1.z, b1.w};
            float vc[8] = {c0.x, c0.y, c0.z, c0.w, c1.x, c1.y, c1.z, c1.w};
            float vd[8] = {d0.x, d0.y, d0.z, d0.w, d1.x, d1.y, d1.z, d1.w};
#pragma unroll
            for (int c = 0; c < 8; c++) {
                float v = __fadd_rn(
                            __fadd_rn(
                              __fadd_rn(__fmul_rn(va[c], w00),
                                        __fmul_rn(vb[c], w01)),
                              __fmul_rn(vc[c], w10)),
                            __fmul_rn(vd[c], w11));
                s_sm[(c * 9 + k) * 128 + px] = v;
            }
        }
#pragma unroll 1
        for (int half = 0; half < 2; half++) {
            __syncthreads();
            for (int i = t; i < 36 * 64; i += 256)
                w_sm[i] = wT[(size_t)(g * 72 + half * 36) * 64 + i];
            __syncthreads();
            const float* srow = s_sm + half * 36 * 128;
#pragma unroll 4
            for (int ck = 0; ck < 36; ck++) {
                u64 sp0 = pk2(srow[ck * 128 + lane],      srow[ck * 128 + lane]);
                u64 sp1 = pk2(srow[ck * 128 + lane + 32], srow[ck * 128 + lane + 32]);
                u64 sp2 = pk2(srow[ck * 128 + lane + 64], srow[ck * 128 + lane + 64]);
                u64 sp3 = pk2(srow[ck * 128 + lane + 96], srow[ck * 128 + lane + 96]);
                const ulonglong2* wq = reinterpret_cast<const ulonglong2*>(w_sm + ck * 64 + obase);
#pragma unroll
                for (int j = 0; j < 2; j++) {
                    ulonglong2 w2 = wq[j];
                    ffma2(acc2[0][2 * j],     sp0, w2.x);
                    ffma2(acc2[0][2 * j + 1], sp0, w2.y);
                    ffma2(acc2[1][2 * j],     sp1, w2.x);
                    ffma2(acc2[1][2 * j + 1], sp1, w2.y);
                    ffma2(acc2[2][2 * j],     sp2, w2.x);
                    ffma2(acc2[2][2 * j + 1], sp2, w2.y);
                    ffma2(acc2[3][2 * j],     sp3, w2.x);
                    ffma2(acc2[3][2 * j + 1], sp3, w2.y);
                }
            }
        }
    }

    float* outrow  = out + (size_t)img * 64 * HW + h * WW;
    float* outTrow = outT ? (outT + ((size_t)img * HW + h * WW) * 64) : nullptr;
#pragma unroll
    for (int o2 = 0; o2 < 4; o2++)
#pragma unroll
        for (int i = 0; i < 4; i++) {
            float alo, ahi;
            upk2(acc2[i][o2], alo, ahi);
            outrow[(size_t)(obase + 2 * o2)     * HW + lane + 32 * i] = alo;
            outrow[(size_t)(obase + 2 * o2 + 1) * HW + lane + 32 * i] = ahi;
            if (outTrow) {
                float2 v2 = make_float2(alo, ahi);
                *reinterpret_cast<float2*>(outTrow + (size_t)(lane + 32 * i) * 64
                                           + obase + 2 * o2) = v2;
            }
        }
}

// ---------------- small utility kernels ----------------
__global__ void transpose_dw_kernel(const float* __restrict__ dw, float* __restrict__ dwT)
{
    int idx = blockIdx.x * blockDim.x + threadIdx.x;
    if (idx < 4 * 64 * 576) {
        int i  = idx / (64 * 576);
        int r  = idx - i * (64 * 576);
        int o  = r / 576;
        int ck = r - o * 576;
        dwT[(size_t)i * (576 * 64) + ck * 64 + o] = dw[idx];
    }
}

__global__ void gather_kernel(const float* __restrict__ t0, float* __restrict__ cat,
                              float* __restrict__ supp, float* __restrict__ suppT)
{
    const size_t total = (size_t)8 * 64 * HW;
    for (size_t idx = (size_t)blockIdx.x * blockDim.x + threadIdx.x; idx < total;
         idx += (size_t)gridDim.x * blockDim.x) {
        int j = (int)(idx / (64 * HW));
        size_t rem = idx - (size_t)j * (64 * HW);
        int c  = (int)(rem >> 14);
        int hw = (int)(rem & (HW - 1));
        int b = j >> 2, slot = j & 3;
        int s = slot + (slot >= 2 ? 1 : 0);
        float ref = t0[(size_t)(b * 5 + 2) * 64 * HW + rem];
        float sp  = t0[(size_t)(b * 5 + s) * 64 * HW + rem];
        cat[(size_t)j * 128 * HW + rem]           = ref;
        cat[((size_t)j * 128 + 64) * HW + rem]    = sp;
        supp[idx] = sp;
        suppT[((size_t)j * HW + hw) * 64 + c] = sp;
    }
}

__global__ void scatter_kernel(const float* __restrict__ x,
                               const float* __restrict__ t0,
                               const float* __restrict__ im,
                               const float* __restrict__ fea,
                               float* __restrict__ out)
{
    const size_t LRS = (size_t)2 * 5 * 3 * HW;
    const size_t TOT = LRS + (size_t)2 * 5 * 64 * HW;
    for (size_t idx = (size_t)blockIdx.x * blockDim.x + threadIdx.x; idx < TOT;
         idx += (size_t)gridDim.x * blockDim.x) {
        if (idx < LRS) {
            int hw = (int)(idx % HW);
            int r  = (int)(idx / HW);
            int c = r % 3; r /= 3;
            int n = r % 5; int b = r / 5;
            float v;
            if (n == 2) {
                v = x[((size_t)(b * 5 + 2) * 3 + c) * HW + hw];
            } else {
                int j = b * 4 + (n < 2 ? n : n - 1);
                v = im[((size_t)j * 3 + c) * HW + hw];
            }
            out[idx] = v;
        } else {
            size_t kk = idx - LRS;
            int hw = (int)(kk % HW);
            int r  = (int)(kk / HW);
            int c = r % 64; r /= 64;
            int n = r % 5; int b = r / 5;
            float v;
            if (n == 2) {
                v = t0[((size_t)(b * 5 + 2) * 64 + c) * HW + hw];
            } else {
                int j = b * 4 + (n < 2 ? n : n - 1);
                v = fea[((size_t)j * 64 + c) * HW + hw];
            }
            out[idx] = v;
        }
    }
}

// ---------------- host ----------------
static void launch_conv8(const float* in, const float* w, const float* b,
                         const float* add, float* out, int Cin, int Cout, int nimg,
                         bool relu, bool addf)
{
    dim3 grid(4, 4, nimg * ((Cout + 7) / 8));
    size_t shmem = (size_t)9 * Cin * 8 * sizeof(float);
    if (relu)      conv3x3_kernel<true,  false><<<grid, 256, shmem>>>(in, w, b, nullptr, out, Cin, Cout);
    else if (addf) conv3x3_kernel<false, true ><<<grid, 256, shmem>>>(in, w, b, add,     out, Cin, Cout);
    else           conv3x3_kernel<false, false><<<grid, 256, shmem>>>(in, w, b, nullptr, out, Cin, Cout);
}

static void launch_conv_sm(const float* in, const float* w, const float* b,
                           const float* add, float* out, int Cout, int nimg,
                           bool relu, bool addf)
{
    dim3 grid(4, 8, nimg * (Cout / 16));
    if (relu) {
        cudaFuncSetAttribute(conv3x3_sm_kernel<true, false>,
                             cudaFuncAttributeMaxDynamicSharedMemorySize, CONV_SM_BYTES);
        conv3x3_sm_kernel<true, false><<<grid, 256, CONV_SM_BYTES>>>(in, w, b, nullptr, out, Cout);
    } else if (addf) {
        cudaFuncSetAttribute(conv3x3_sm_kernel<false, true>,
                             cudaFuncAttributeMaxDynamicSharedMemorySize, CONV_SM_BYTES);
        conv3x3_sm_kernel<false, true><<<grid, 256, CONV_SM_BYTES>>>(in, w, b, add, out, Cout);
    } else {
        cudaFuncSetAttribute(conv3x3_sm_kernel<false, false>,
                             cudaFuncAttributeMaxDynamicSharedMemorySize, CONV_SM_BYTES);
        conv3x3_sm_kernel<false, false><<<grid, 256, CONV_SM_BYTES>>>(in, w, b, nullptr, out, Cout);
    }
}

extern "C" void kernel_launch(void* const* d_in, const int* in_sizes, int n_in,
                              void* d_out, int out_size)
{
    const float* x    = (const float*)d_in[0];
    const float* cfw  = (const float*)d_in[1];
    const float* cfb  = (const float*)d_in[2];
    const float* rw1  = (const float*)d_in[3];
    const float* rb1  = (const float*)d_in[4];
    const float* rw2  = (const float*)d_in[5];
    const float* rb2  = (const float*)d_in[6];
    const float* crw  = (const float*)d_in[7];
    const float* crb  = (const float*)d_in[8];
    const float* offw = (const float*)d_in[9];
    const float* offb = (const float*)d_in[10];
    const float* dw   = (const float*)d_in[11];
    const float* rcw  = (const float*)d_in[12];
    const float* rcb  = (const float*)d_in[13];
    float* out = (float*)d_out;

    float *t0, *rbuf, *cat, *supp, *feaA, *feaB, *offbuf, *im, *dwT, *srcT, *suppT, *srcTB;
    cudaGetSymbolAddress((void**)&t0,    g_t0);
    cudaGetSymbolAddress((void**)&rbuf,  g_r);
    cudaGetSymbolAddress((void**)&cat,   g_cat);
    cudaGetSymbolAddress((void**)&supp,  g_supp);
    cudaGetSymbolAddress((void**)&feaA,  g_feaA);
    cudaGetSymbolAddress((void**)&feaB,  g_feaB);
    cudaGetSymbolAddress((void**)&offbuf,g_off);
    cudaGetSymbolAddress((void**)&im,    g_im);
    cudaGetSymbolAddress((void**)&dwT,   g_dwT);
    cudaGetSymbolAddress((void**)&srcT,  g_srcT);
    cudaGetSymbolAddress((void**)&suppT, g_suppT);
    cudaGetSymbolAddress((void**)&srcTB, g_srcTB);

    transpose_dw_kernel<<<(4 * 64 * 576 + 255) / 256, 256>>>(dw, dwT);

    // conv_first + ReLU : (10,3) -> (10,64)
    launch_conv8(x, cfw, cfb, nullptr, t0, 3, 64, 10, true, false);

    // 5 residual blocks (R12 launch shape)
    for (int i = 0; i < 5; i++) {
        launch_conv_sm(t0,   rw1 + (size_t)i * 36864, rb1 + i * 64, nullptr, rbuf, 64, 10, true,  false);
        launch_conv_sm(rbuf, rw2 + (size_t)i * 36864, rb2 + i * 64, t0,      t0,   64, 10, false, true);
    }

    // build concat(ref, supp), supp and px-major suppT
    gather_kernel<<<4096, 256>>>(t0, cat, supp, suppT);

    // cr conv: 128 -> 64
    launch_conv8(cat, crw, crb, nullptr, feaA, 128, 64, 8, false, false);

    const dim3 tgrid(512, 2, 8);
    const dim3 dgrid(128, 8);

    // PCD cascade (transpose fusion: dual-output deform feeds the next stage)
    launch_conv_sm(feaA, offw,              offb,       nullptr, offbuf, 144, 8, false, false);
    transpose_src_kernel<<<tgrid, 256>>>(feaA, srcT);
    deform_conv_kernel<<<dgrid, 256>>>(srcT, offbuf, dwT,              feaB, srcTB);

    launch_conv_sm(feaB, offw + 82944,      offb + 144, nullptr, offbuf, 144, 8, false, false);
    deform_conv_kernel<<<dgrid, 256>>>(srcTB, offbuf, dwT + 36864,     feaA, nullptr);

    launch_conv_sm(feaA, offw + 2 * 82944,  offb + 288, nullptr, offbuf, 144, 8, false, false);
    deform_conv_kernel<<<dgrid, 256>>>(suppT, offbuf, dwT + 2 * 36864, feaB, srcTB);   // fea

    launch_conv_sm(feaB, offw + 3 * 82944,  offb + 432, nullptr, offbuf, 144, 8, false, false);
    deform_conv_kernel<<<dgrid, 256>>>(srcTB, offbuf, dwT + 3 * 36864, feaA, nullptr); // aligned

    // recon conv: 64 -> 3
    launch_conv8(feaA, rcw, rcb, nullptr, im, 64, 3, 8, false, false);

    // assemble outputs (lrs | feats)
    scatter_kernel<<<4096, 256>>>(x, t0, im, feaB, out);
}

// round 16
// speedup vs baseline: 1.1282x; 1.0369x over previous
#include <cuda_runtime.h>

#define HH 128
#define WW 128
#define HW 16384

typedef unsigned long long u64;

__device__ __forceinline__ u64 pk2(float lo, float hi) {
    u64 r; asm("mov.b64 %0, {%1,%2};" : "=l"(r) : "f"(lo), "f"(hi)); return r;
}
__device__ __forceinline__ void upk2(u64 v, float& lo, float& hi) {
    asm("mov.b64 {%0,%1}, %2;" : "=f"(lo), "=f"(hi) : "l"(v));
}
__device__ __forceinline__ void ffma2(u64& d, u64 a, u64 b) {
    asm("fma.rn.f32x2 %0, %1, %2, %3;" : "=l"(d) : "l"(a), "l"(b), "l"(d));
}

// ---------------- scratch ----------------
__device__ float g_t0   [10 * 64 * HW];
__device__ float g_r    [10 * 64 * HW];
__device__ float g_cat  [8 * 128 * HW];
__device__ float g_supp [8 * 64 * HW];
__device__ float g_feaA [8 * 64 * HW];
__device__ float g_feaB [8 * 64 * HW];
__device__ float g_off  [8 * 144 * HW];
__device__ float g_im   [8 * 3 * HW];
__device__ float g_dwT  [4 * 576 * 64];
__device__ float g_srcT [8 * 64 * HW];   // px-major deform input (transpose kernel)
__device__ float g_suppT[8 * 64 * HW];   // px-major supp (from gather)

// ================= smem-staged conv (R12 winner): Cin=64, 16 outs, 32x16, 256 thr ====
#define SPX   612          // 18*34
#define SPAD  65
#define CONV_SM_BYTES ((SPX * SPAD + 9 * 64 * 16) * 4)

template <bool RELU, bool ADD>
__global__ __launch_bounds__(256)
void conv3x3_sm_kernel(const float* __restrict__ in, const float* __restrict__ wgt,
                       const float* __restrict__ bias, const float* __restrict__ addsrc,
                       float* __restrict__ out, int Cout)
{
    const int CIN = 64;
    const int ogroups = Cout >> 4;
    const int img   = blockIdx.z / ogroups;
    const int og    = blockIdx.z - img * ogroups;
    const int obase = og << 4;
    const int tx0   = blockIdx.x << 5;   // 32-wide
    const int ty0   = blockIdx.y << 4;   // 16-high

    extern __shared__ float sm[];
    float* ssm = sm;                     // [px][c] stride SPAD
    float* wsm = sm + SPX * SPAD;        // [kk][c][16]

    const int t = threadIdx.x;

    {
        const float* inimg = in + (size_t)img * CIN * HW;
#pragma unroll
        for (int i0 = 0; i0 < 3; i0++) {
            int px = t + i0 * 256;
            if (px < SPX) {
                int r   = px / 34;
                int col = px - r * 34;
                int gy  = ty0 + r - 1;
                int gx  = tx0 + col - 1;
                float* dst = ssm + px * SPAD;
                if ((unsigned)gy < HH && (unsigned)gx < WW) {
                    const float* src = inimg + gy * WW + gx;
#pragma unroll 8
                    for (int c = 0; c < CIN; c++) dst[c] = __ldg(src + (size_t)c * HW);
                } else {
#pragma unroll 8
                    for (int c = 0; c < CIN; c++) dst[c] = 0.f;
                }
            }
        }
        for (int i = t; i < 9 * CIN * 16; i += 256) {
            int o  = i & 15;
            int r  = i >> 4;
            int kk = r >> 6;
            int c  = r & 63;
            wsm[i] = wgt[((size_t)(obase + o) * CIN + c) * 9 + kk];
        }
    }
    __syncthreads();

    const int col = t & 31;
    const int row = t >> 5;              // 0..7 ; rows row, row+8

    u64 acc2[2][8];
#pragma unroll
    for (int p = 0; p < 2; p++)
#pragma unroll
        for (int o2 = 0; o2 < 8; o2++) acc2[p][o2] = 0ull;

#pragma unroll 1
    for (int kk = 0; kk < 9; kk++) {
        const int ky = kk / 3;
        const int kx = kk - ky * 3;
        const float* p0 = ssm + ((row + ky) * 34 + col + kx) * SPAD;
        const float* p1 = p0 + 8 * 34 * SPAD;
        const float* wrow = wsm + kk * CIN * 16;
#pragma unroll 16
        for (int c = 0; c < CIN; c++) {
            float v0 = p0[c];
            float v1 = p1[c];
            u64 vp0 = pk2(v0, v0);
            u64 vp1 = pk2(v1, v1);
            const ulonglong2* wq = reinterpret_cast<const ulonglong2*>(wrow + c * 16);
#pragma unroll
            for (int j = 0; j < 4; j++) {
                ulonglong2 w2 = wq[j];
                ffma2(acc2[0][2 * j],     vp0, w2.x);
                ffma2(acc2[0][2 * j + 1], vp0, w2.y);
                ffma2(acc2[1][2 * j],     vp1, w2.x);
                ffma2(acc2[1][2 * j + 1], vp1, w2.y);
            }
        }
    }

    float* outimg = out + (size_t)img * Cout * HW;
    const float* addimg = ADD ? (addsrc + (size_t)img * Cout * HW) : nullptr;
    const int gx = tx0 + col;
#pragma unroll
    for (int o2 = 0; o2 < 8; o2++) {
#pragma unroll
        for (int p = 0; p < 2; p++) {
            float alo, ahi;
            upk2(acc2[p][o2], alo, ahi);
            int gy = ty0 + row + 8 * p;
#pragma unroll
            for (int half = 0; half < 2; half++) {
                int oc = obase + 2 * o2 + half;
                float val = (half ? ahi : alo) + bias[oc];
                size_t oi = (size_t)oc * HW + gy * WW + gx;
                if (ADD)  val += addimg[oi];
                if (RELU) val = fmaxf(val, 0.f);
                outimg[oi] = val;
            }
        }
    }
}

// ---------------- generic 3x3 conv, 8 outs/block (Cin=3/128, Cout=3) ----------------
template <bool RELU, bool ADD>
__global__ __launch_bounds__(256)
void conv3x3_kernel(const float* __restrict__ in, const float* __restrict__ wgt,
                    const float* __restrict__ bias, const float* __restrict__ addsrc,
                    float* __restrict__ out, int Cin, int Cout)
{
    const int ogroups = (Cout + 7) >> 3;
    const int img   = blockIdx.z / ogroups;
    const int og    = blockIdx.z - img * ogroups;
    const int obase = og << 3;
    const int tx0   = blockIdx.x << 5;
    const int ty0   = blockIdx.y << 5;

    extern __shared__ float wsm8[];   // [kk][c][8]

    const int t    = threadIdx.x;
    const int col  = t & 31;
    const int row0 = (t >> 5) << 2;

    for (int i = t; i < 9 * Cin * 8; i += 256) {
        int o  = i & 7;
        int r  = i >> 3;
        int kk = r / Cin;
        int c  = r - kk * Cin;
        wsm8[i] = (obase + o < Cout)
                 ? wgt[((size_t)(obase + o) * Cin + c) * 9 + kk] : 0.f;
    }
    __syncthreads();

    u64 acc2[4][4];
#pragma unroll
    for (int p = 0; p < 4; p++)
#pragma unroll
        for (int o2 = 0; o2 < 4; o2++) acc2[p][o2] = 0ull;

    const float* inimg = in + (size_t)img * Cin * HW;

#pragma unroll 1
    for (int kk = 0; kk < 9; kk++) {
        const int ky = kk / 3 - 1;
        const int kx = kk - (kk / 3) * 3 - 1;
        const int gx = tx0 + col + kx;
        const bool xin = ((unsigned)gx < WW);
        const float* bp[4];
        bool inb[4];
#pragma unroll
        for (int p = 0; p < 4; p++) {
            int gy = ty0 + row0 + p + ky;
            inb[p] = xin && ((unsigned)gy < HH);
            bp[p]  = inimg + gy * WW + gx;
        }
        const float* wrow = wsm8 + kk * Cin * 8;
#pragma unroll 4
        for (int c = 0; c < Cin; c++) {
            float v0 = inb[0] ? __ldg(bp[0] + (size_t)c * HW) : 0.f;
            float v1 = inb[1] ? __ldg(bp[1] + (size_t)c * HW) : 0.f;
            float v2 = inb[2] ? __ldg(bp[2] + (size_t)c * HW) : 0.f;
            float v3 = inb[3] ? __ldg(bp[3] + (size_t)c * HW) : 0.f;
            u64 vp0 = pk2(v0, v0);
            u64 vp1 = pk2(v1, v1);
            u64 vp2 = pk2(v2, v2);
            u64 vp3 = pk2(v3, v3);
            const float* wc = wrow + c * 8;
#pragma unroll
            for (int o2 = 0; o2 < 4; o2++) {
                u64 wp = *reinterpret_cast<const u64*>(wc + 2 * o2);
                ffma2(acc2[0][o2], vp0, wp);
                ffma2(acc2[1][o2], vp1, wp);
                ffma2(acc2[2][o2], vp2, wp);
                ffma2(acc2[3][o2], vp3, wp);
            }
        }
    }

    float* outimg = out + (size_t)img * Cout * HW;
    const float* addimg = ADD ? (addsrc + (size_t)img * Cout * HW) : nullptr;
#pragma unroll
    for (int o2 = 0; o2 < 4; o2++) {
#pragma unroll
        for (int p = 0; p < 4; p++) {
            float alo, ahi;
            upk2(acc2[p][o2], alo, ahi);
            int gy = ty0 + row0 + p;
            int gx = tx0 + col;
#pragma unroll
            for (int half = 0; half < 2; half++) {
                int oc = obase + 2 * o2 + half;
                if (oc < Cout) {
                    float val = (half ? ahi : alo) + bias[oc];
                    size_t oi = (size_t)oc * HW + gy * WW + gx;
                    if (ADD)  val += addimg[oi];
                    if (RELU) val = fmaxf(val, 0.f);
                    outimg[oi] = val;
                }
            }
        }
    }
}

// ---------------- transpose (64,HW) -> (HW,64) per image ----------------
__global__ __launch_bounds__(256)
void transpose_src_kernel(const float* __restrict__ in, float* __restrict__ out)
{
    __shared__ float tl[32][33];
    const int p0  = blockIdx.x << 5;
    const int c0  = blockIdx.y << 5;
    const int img = blockIdx.z;
    const float* ii = in  + (size_t)img * 64 * HW;
    float*       oo = out + (size_t)img * 64 * HW;
    const int tx = threadIdx.x & 31;
    const int ty = threadIdx.x >> 5;
#pragma unroll
    for (int j = 0; j < 4; j++) {
        int c = c0 + ty + j * 8;
        tl[ty + j * 8][tx] = ii[(size_t)c * HW + p0 + tx];
    }
    __syncthreads();
#pragma unroll
    for (int j = 0; j < 4; j++) {
        int p = p0 + ty + j * 8;
        oo[(size_t)p * 64 + c0 + tx] = tl[tx][ty + j * 8];
    }
}

// ---------------- grouped deformable conv (G=8, K2=9, Cpg=8) ----------------
__global__ __launch_bounds__(256)
void deform_conv_kernel(const float* __restrict__ srcT,  // (8,HW,64) pixel-major
                        const float* __restrict__ off,   // (8,144,HW)
                        const float* __restrict__ wT,    // [576][64]
                        float* __restrict__ out)         // (8,64,HW)
{
    const int h   = blockIdx.x;
    const int img = blockIdx.y;

    __shared__ float s_sm[72 * 128];
    __shared__ float w_sm[36 * 64];

    const int t     = threadIdx.x;
    const int lane  = t & 31;
    const int obase = (t >> 5) << 3;

    u64 acc2[4][4];
#pragma unroll
    for (int i = 0; i < 4; i++)
#pragma unroll
        for (int o2 = 0; o2 < 4; o2++) acc2[i][o2] = 0ull;

    const float* simg   = srcT + (size_t)img * 64 * HW;
    const float* offrow = off  + (size_t)img * 144 * HW + h * WW;

    for (int g = 0; g < 8; g++) {
        __syncthreads();
        for (int task = t; task < 1152; task += 256) {
            const int px = task & 127;
            const int k  = task >> 7;
            float dy = offrow[(size_t)((g * 9 + k) * 2)     * HW + px];
            float dx = offrow[(size_t)((g * 9 + k) * 2 + 1) * HW + px];
            float py = __fadd_rn(__fadd_rn(dy, (float)h),  (float)(k / 3 - 1));
            float qx = __fadd_rn(__fadd_rn(dx, (float)px), (float)(k % 3 - 1));
            float y0f = floorf(py), x0f = floorf(qx);
            float wy = __fsub_rn(py, y0f), wx = __fsub_rn(qx, x0f);
            bool my0 = (y0f >=  0.f) && (y0f <= (float)(HH - 1));
            bool my1 = (y0f >= -1.f) && (y0f <= (float)(HH - 2));
            bool mx0 = (x0f >=  0.f) && (x0f <= (float)(WW - 1));
            bool mx1 = (x0f >= -1.f) && (x0f <= (float)(WW - 2));
            int yi0 = (int)fminf(fmaxf(y0f,       0.f), (float)(HH - 1));
            int xi0 = (int)fminf(fmaxf(x0f,       0.f), (float)(WW - 1));
            int yi1 = (int)fminf(fmaxf(y0f + 1.f, 0.f), (float)(HH - 1));
            int xi1 = (int)fminf(fmaxf(x0f + 1.f, 0.f), (float)(WW - 1));
            float omy = __fsub_rn(1.f, wy), omx = __fsub_rn(1.f, wx);
            float w00 = __fmul_rn(__fmul_rn(omy, omx), (my0 && mx0) ? 1.f : 0.f);
            float w01 = __fmul_rn(__fmul_rn(omy, wx),  (my0 && mx1) ? 1.f : 0.f);
            float w10 = __fmul_rn(__fmul_rn(wy, omx),  (my1 && mx0) ? 1.f : 0.f);
            float w11 = __fmul_rn(__fmul_rn(wy, wx),   (my1 && mx1) ? 1.f : 0.f);
            int i00 = yi0 * WW + xi0, i01 = yi0 * WW + xi1;
            int i10 = yi1 * WW + xi0, i11 = yi1 * WW + xi1;
            const int g8 = g * 8;
            const float4* q00 = reinterpret_cast<const float4*>(simg + (size_t)i00 * 64 + g8);
            const float4* q01 = reinterpret_cast<const float4*>(simg + (size_t)i01 * 64 + g8);
            const float4* q10 = reinterpret_cast<const float4*>(simg + (size_t)i10 * 64 + g8);
            const float4* q11 = reinterpret_cast<const float4*>(simg + (size_t)i11 * 64 + g8);
            float4 a0 = q00[0], a1 = q00[1];
            float4 b0 = q01[0], b1 = q01[1];
            float4 c0 = q10[0], c1 = q10[1];
            float4 d0 = q11[0], d1 = q11[1];
            float va[8] = {a0.x, a0.y, a0.z, a0.w, a1.x, a1.y, a1.z, a1.w};
            float vb[8] = {b0.x, b0.y, b0.z, b0.w, b1.x, b1.y, b1.z, b1.w};
            float vc[8] = {c0.x, c0.y, c0.z, c0.w, c1.x, c1.y, c1.z, c1.w};
            float vd[8] = {d0.x, d0.y, d0.z, d0.w, d1.x, d1.y, d1.z, d1.w};
#pragma unroll
            for (int c = 0; c < 8; c++) {
                float v = __fadd_rn(
                            __fadd_rn(
                              __fadd_rn(__fmul_rn(va[c], w00),
                                        __fmul_rn(vb[c], w01)),
                              __fmul_rn(vc[c], w10)),
                            __fmul_rn(vd[c], w11));
                s_sm[(c * 9 + k) * 128 + px] = v;
            }
        }
#pragma unroll 1
        for (int half = 0; half < 2; half++) {
            __syncthreads();
            for (int i = t; i < 36 * 64; i += 256)
                w_sm[i] = wT[(size_t)(g * 72 + half * 36) * 64 + i];
            __syncthreads();
            const float* srow = s_sm + half * 36 * 128;
#pragma unroll 4
            for (int ck = 0; ck < 36; ck++) {
                u64 sp0 = pk2(srow[ck * 128 + lane],      srow[ck * 128 + lane]);
                u64 sp1 = pk2(srow[ck * 128 + lane + 32], srow[ck * 128 + lane + 32]);
                u64 sp2 = pk2(srow[ck * 128 + lane + 64], srow[ck * 128 + lane + 64]);
                u64 sp3 = pk2(srow[ck * 128 + lane + 96], srow[ck * 128 + lane + 96]);
                const ulonglong2* wq = reinterpret_cast<const ulonglong2*>(w_sm + ck * 64 + obase);
#pragma unroll
                for (int j = 0; j < 2; j++) {
                    ulonglong2 w2 = wq[j];
                    ffma2(acc2[0][2 * j],     sp0, w2.x);
                    ffma2(acc2[0][2 * j + 1], sp0, w2.y);
                    ffma2(acc2[1][2 * j],     sp1, w2.x);
                    ffma2(acc2[1][2 * j + 1], sp1, w2.y);
                    ffma2(acc2[2][2 * j],     sp2, w2.x);
                    ffma2(acc2[2][2 * j + 1], sp2, w2.y);
                    ffma2(acc2[3][2 * j],     sp3, w2.x);
                    ffma2(acc2[3][2 * j + 1], sp3, w2.y);
                }
            }
        }
    }

    float* outrow = out + (size_t)img * 64 * HW + h * WW;
#pragma unroll
    for (int o2 = 0; o2 < 4; o2++)
#pragma unroll
        for (int i = 0; i < 4; i++) {
            float alo, ahi;
            upk2(acc2[i][o2], alo, ahi);
            outrow[(size_t)(obase + 2 * o2)     * HW + lane + 32 * i] = alo;
            outrow[(size_t)(obase + 2 * o2 + 1) * HW + lane + 32 * i] = ahi;
        }
}

// ---------------- small utility kernels ----------------
__global__ void transpose_dw_kernel(const float* __restrict__ dw, float* __restrict__ dwT)
{
    int idx = blockIdx.x * blockDim.x + threadIdx.x;
    if (idx < 4 * 64 * 576) {
        int i  = idx / (64 * 576);
        int r  = idx - i * (64 * 576);
        int o  = r / 576;
        int ck = r - o * 576;
        dwT[(size_t)i * (576 * 64) + ck * 64 + o] = dw[idx];
    }
}

__global__ void gather_kernel(const float* __restrict__ t0, float* __restrict__ cat,
                              float* __restrict__ supp, float* __restrict__ suppT)
{
    const size_t total = (size_t)8 * 64 * HW;
    for (size_t idx = (size_t)blockIdx.x * blockDim.x + threadIdx.x; idx < total;
         idx += (size_t)gridDim.x * blockDim.x) {
        int j = (int)(idx / (64 * HW));
        size_t rem = idx - (size_t)j * (64 * HW);
        int c  = (int)(rem >> 14);
        int hw = (int)(rem & (HW - 1));
        int b = j >> 2, slot = j & 3;
        int s = slot + (slot >= 2 ? 1 : 0);
        float ref = t0[(size_t)(b * 5 + 2) * 64 * HW + rem];
        float sp  = t0[(size_t)(b * 5 + s) * 64 * HW + rem];
        cat[(size_t)j * 128 * HW + rem]           = ref;
        cat[((size_t)j * 128 + 64) * HW + rem]    = sp;
        supp[idx] = sp;
        suppT[((size_t)j * HW + hw) * 64 + c] = sp;
    }
}

__global__ void scatter_kernel(const float* __restrict__ x,
                               const float* __restrict__ t0,
                               const float* __restrict__ im,
                               const float* __restrict__ fea,
                               float* __restrict__ out)
{
    const size_t LRS = (size_t)2 * 5 * 3 * HW;
    const size_t TOT = LRS + (size_t)2 * 5 * 64 * HW;
    for (size_t idx = (size_t)blockIdx.x * blockDim.x + threadIdx.x; idx < TOT;
         idx += (size_t)gridDim.x * blockDim.x) {
        if (idx < LRS) {
            int hw = (int)(idx % HW);
            int r  = (int)(idx / HW);
            int c = r % 3; r /= 3;
            int n = r % 5; int b = r / 5;
            float v;
            if (n == 2) {
                v = x[((size_t)(b * 5 + 2) * 3 + c) * HW + hw];
            } else {
                int j = b * 4 + (n < 2 ? n : n - 1);
                v = im[((size_t)j * 3 + c) * HW + hw];
            }
            out[idx] = v;
        } else {
            size_t kk = idx - LRS;
            int hw = (int)(kk % HW);
            int r  = (int)(kk / HW);
            int c = r % 64; r /= 64;
            int n = r % 5; int b = r / 5;
            float v;
            if (n == 2) {
                v = t0[((size_t)(b * 5 + 2) * 64 + c) * HW + hw];
            } else {
                int j = b * 4 + (n < 2 ? n : n - 1);
                v = fea[((size_t)j * 64 + c) * HW + hw];
            }
            out[idx] = v;
        }
    }
}

// ---------------- host ----------------
static void launch_conv8(const float* in, const float* w, const float* b,
                         const float* add, float* out, int Cin, int Cout, int nimg,
                         bool relu, bool addf)
{
    dim3 grid(4, 4, nimg * ((Cout + 7) / 8));
    size_t shmem = (size_t)9 * Cin * 8 * sizeof(float);
    if (relu)      conv3x3_kernel<true,  false><<<grid, 256, shmem>>>(in, w, b, nullptr, out, Cin, Cout);
    else if (addf) conv3x3_kernel<false, true ><<<grid, 256, shmem>>>(in, w, b, add,     out, Cin, Cout);
    else           conv3x3_kernel<false, false><<<grid, 256, shmem>>>(in, w, b, nullptr, out, Cin, Cout);
}

static void launch_conv_sm(const float* in, const float* w, const float* b,
                           const float* add, float* out, int Cout, int nimg,
                           bool relu, bool addf)
{
    dim3 grid(4, 8, nimg * (Cout / 16));
    if (relu) {
        cudaFuncSetAttribute(conv3x3_sm_kernel<true, false>,
                             cudaFuncAttributeMaxDynamicSharedMemorySize, CONV_SM_BYTES);
        conv3x3_sm_kernel<true, false><<<grid, 256, CONV_SM_BYTES>>>(in, w, b, nullptr, out, Cout);
    } else if (addf) {
        cudaFuncSetAttribute(conv3x3_sm_kernel<false, true>,
                             cudaFuncAttributeMaxDynamicSharedMemorySize, CONV_SM_BYTES);
        conv3x3_sm_kernel<false, true><<<grid, 256, CONV_SM_BYTES>>>(in, w, b, add, out, Cout);
    } else {
        cudaFuncSetAttribute(conv3x3_sm_kernel<false, false>,
                             cudaFuncAttributeMaxDynamicSharedMemorySize, CONV_SM_BYTES);
        conv3x3_sm_kernel<false, false><<<grid, 256, CONV_SM_BYTES>>>(in, w, b, nullptr, out, Cout);
    }
}

extern "C" void kernel_launch(void* const* d_in, const int* in_sizes, int n_in,
                              void* d_out, int out_size)
{
    const float* x    = (const float*)d_in[0];
    const float* cfw  = (const float*)d_in[1];
    const float* cfb  = (const float*)d_in[2];
    const float* rw1  = (const float*)d_in[3];
    const float* rb1  = (const float*)d_in[4];
    const float* rw2  = (const float*)d_in[5];
    const float* rb2  = (const float*)d_in[6];
    const float* crw  = (const float*)d_in[7];
    const float* crb  = (const float*)d_in[8];
    const float* offw = (const float*)d_in[9];
    const float* offb = (const float*)d_in[10];
    const float* dw   = (const float*)d_in[11];
    const float* rcw  = (const float*)d_in[12];
    const float* rcb  = (const float*)d_in[13];
    float* out = (float*)d_out;

    float *t0, *rbuf, *cat, *supp, *feaA, *feaB, *offbuf, *im, *dwT, *srcT, *suppT;
    cudaGetSymbolAddress((void**)&t0,    g_t0);
    cudaGetSymbolAddress((void**)&rbuf,  g_r);
    cudaGetSymbolAddress((void**)&cat,   g_cat);
    cudaGetSymbolAddress((void**)&supp,  g_supp);
    cudaGetSymbolAddress((void**)&feaA,  g_feaA);
    cudaGetSymbolAddress((void**)&feaB,  g_feaB);
    cudaGetSymbolAddress((void**)&offbuf,g_off);
    cudaGetSymbolAddress((void**)&im,    g_im);
    cudaGetSymbolAddress((void**)&dwT,   g_dwT);
    cudaGetSymbolAddress((void**)&srcT,  g_srcT);
    cudaGetSymbolAddress((void**)&suppT, g_suppT);

    transpose_dw_kernel<<<(4 * 64 * 576 + 255) / 256, 256>>>(dw, dwT);

    // conv_first + ReLU : (10,3) -> (10,64)
    launch_conv8(x, cfw, cfb, nullptr, t0, 3, 64, 10, true, false);

    // 5 residual blocks
    for (int i = 0; i < 5; i++) {
        launch_conv_sm(t0,   rw1 + (size_t)i * 36864, rb1 + i * 64, nullptr, rbuf, 64, 10, true,  false);
        launch_conv_sm(rbuf, rw2 + (size_t)i * 36864, rb2 + i * 64, t0,      t0,   64, 10, false, true);
    }

    // build concat(ref, supp), supp and px-major suppT
    gather_kernel<<<4096, 256>>>(t0, cat, supp, suppT);

    // cr conv: 128 -> 64
    launch_conv8(cat, crw, crb, nullptr, feaA, 128, 64, 8, false, false);

    const dim3 tgrid(512, 2, 8);
    const dim3 dgrid(128, 8);

    // PCD cascade (transpose before each deform; supp's transpose comes from gather)
    launch_conv_sm(feaA, offw,              offb,       nullptr, offbuf, 144, 8, false, false);
    transpose_src_kernel<<<tgrid, 256>>>(feaA, srcT);
    deform_conv_kernel<<<dgrid, 256>>>(srcT, offbuf, dwT,              feaB);

    launch_conv_sm(feaB, offw + 82944,      offb + 144, nullptr, offbuf, 144, 8, false, false);
    transpose_src_kernel<<<tgrid, 256>>>(feaB, srcT);
    deform_conv_kernel<<<dgrid, 256>>>(srcT, offbuf, dwT + 36864,      feaA);

    launch_conv_sm(feaA, offw + 2 * 82944,  offb + 288, nullptr, offbuf, 144, 8, false, false);
    deform_conv_kernel<<<dgrid, 256>>>(suppT, offbuf, dwT + 2 * 36864, feaB);   // fea

    launch_conv_sm(feaB, offw + 3 * 82944,  offb + 432, nullptr, offbuf, 144, 8, false, false);
    transpose_src_kernel<<<tgrid, 256>>>(feaB, srcT);
    deform_conv_kernel<<<dgrid, 256>>>(srcT, offbuf, dwT + 3 * 36864,  feaA);   // aligned

    // recon conv: 64 -> 3
    launch_conv8(feaA, rcw, rcb, nullptr, im, 64, 3, 8, false, false);

    // assemble outputs (lrs | feats)
    scatter_kernel<<<4096, 256>>>(x, t0, im, feaB, out);
}